// round 4
// baseline (speedup 1.0000x reference)
#include <cuda_runtime.h>

#define NQ   14
#define DIM  (1 << NQ)       // 16384
#define NL   3
#define TPB  512
#define SMEM_BYTES (DIM * sizeof(float2))   // 131072

__global__ __launch_bounds__(TPB, 1)
void qsim_kernel(const float* __restrict__ x,
                 const float* __restrict__ qw,
                 const float* __restrict__ wlin,
                 const float* __restrict__ blin,
                 float* __restrict__ out)
{
    extern __shared__ float2 s[];         // statevector, 128 KB
    __shared__ float red[TPB / 32];

    const int b   = blockIdx.x;
    const int tid = threadIdx.x;

    // ---- init |0...0> ----
    for (int i = tid; i < DIM; i += TPB)
        s[i] = make_float2(0.0f, 0.0f);
    if (tid == 0) s[0] = make_float2(1.0f, 0.0f);

    // ---- AngleEmbedding: RX(x_w) on wire w (wire w <-> bit 13-w) ----
    for (int w = 0; w < NQ; w++) {
        float h = 0.5f * x[b * NQ + w];
        float c, sn;
        sincosf(h, &sn, &c);
        int bb = NQ - 1 - w;
        unsigned lowm = (1u << bb) - 1u;
        __syncthreads();
        for (int p = tid; p < DIM / 2; p += TPB) {
            unsigned i0 = (((unsigned)p >> bb) << (bb + 1)) | ((unsigned)p & lowm);
            unsigned i1 = i0 | (1u << bb);
            float2 a0 = s[i0];
            float2 a1 = s[i1];
            // RX = [[c, -i sn], [-i sn, c]]
            float2 n0, n1;
            n0.x = c * a0.x + sn * a1.y;
            n0.y = c * a0.y - sn * a1.x;
            n1.x = sn * a0.y + c * a1.x;
            n1.y = -sn * a0.x + c * a1.y;
            s[i0] = n0;
            s[i1] = n1;
        }
    }

    // ---- StronglyEntanglingLayers ----
    for (int l = 0; l < NL; l++) {
        // Rot on each wire
        for (int w = 0; w < NQ; w++) {
            float phi = qw[(l * NQ + w) * 3 + 0];
            float th  = qw[(l * NQ + w) * 3 + 1];
            float om  = qw[(l * NQ + w) * 3 + 2];
            float ct, st, ca, sa, cb, sb;
            sincosf(0.5f * th, &st, &ct);
            sincosf(0.5f * (phi + om), &sa, &ca);
            sincosf(0.5f * (phi - om), &sb, &cb);
            // Rot = [[e^{-i(phi+om)/2} ct, -e^{+i(phi-om)/2} st],
            //        [e^{-i(phi-om)/2} st,  e^{+i(phi+om)/2} ct]]
            float g00r =  ct * ca, g00i = -ct * sa;
            float g01r = -st * cb, g01i = -st * sb;
            float g10r =  st * cb, g10i = -st * sb;
            float g11r =  ct * ca, g11i =  ct * sa;

            int bb = NQ - 1 - w;
            unsigned lowm = (1u << bb) - 1u;
            __syncthreads();
            for (int p = tid; p < DIM / 2; p += TPB) {
                unsigned i0 = (((unsigned)p >> bb) << (bb + 1)) | ((unsigned)p & lowm);
                unsigned i1 = i0 | (1u << bb);
                float2 a0 = s[i0];
                float2 a1 = s[i1];
                float2 n0, n1;
                n0.x = g00r * a0.x - g00i * a0.y + g01r * a1.x - g01i * a1.y;
                n0.y = g00r * a0.y + g00i * a0.x + g01r * a1.y + g01i * a1.x;
                n1.x = g10r * a0.x - g10i * a0.y + g11r * a1.x - g11i * a1.y;
                n1.y = g10r * a0.y + g10i * a0.x + g11r * a1.y + g11i * a1.x;
                s[i0] = n0;
                s[i1] = n1;
            }
        }
        // CNOT ring: control w, target (w+r)%n, r = l+1
        int r = l + 1;
        for (int w = 0; w < NQ; w++) {
            int bc = NQ - 1 - w;               // control bit
            int bt = NQ - 1 - ((w + r) % NQ);  // target bit
            int hi = bc > bt ? bc : bt;
            int lo = bc > bt ? bt : bc;
            unsigned lowmask = (1u << lo) - 1u;
            unsigned himask  = (1u << hi) - 1u;
            __syncthreads();
            for (int p = tid; p < DIM / 4; p += TPB) {
                unsigned t1 = (((unsigned)p >> lo) << (lo + 1)) | ((unsigned)p & lowmask);
                unsigned i0 = ((t1 >> hi) << (hi + 1)) | (t1 & himask);
                i0 |= (1u << bc);              // control = 1, target = 0
                unsigned i1 = i0 | (1u << bt); // control = 1, target = 1
                float2 a0 = s[i0];
                float2 a1 = s[i1];
                s[i0] = a1;                    // swap amplitudes
                s[i1] = a0;
            }
        }
    }
    __syncthreads();

    // ---- probs -> <Z_w> -> linear head, fused ----
    float wl[NQ];
    #pragma unroll
    for (int w = 0; w < NQ; w++) wl[w] = wlin[w];

    float acc = 0.0f;
    for (int i = tid; i < DIM; i += TPB) {
        float2 a = s[i];
        float  pr = a.x * a.x + a.y * a.y;
        float  z = 0.0f;
        #pragma unroll
        for (int w = 0; w < NQ; w++)
            z += (((unsigned)i >> (NQ - 1 - w)) & 1u) ? -wl[w] : wl[w];
        acc += pr * z;
    }
    #pragma unroll
    for (int off = 16; off; off >>= 1)
        acc += __shfl_down_sync(0xffffffffu, acc, off);
    if ((tid & 31) == 0) red[tid >> 5] = acc;
    __syncthreads();
    if (tid == 0) {
        float t = 0.0f;
        #pragma unroll
        for (int q = 0; q < TPB / 32; q++) t += red[q];
        out[b] = t + blin[0];
    }
}

extern "C" void kernel_launch(void* const* d_in, const int* in_sizes, int n_in,
                              void* d_out, int out_size)
{
    // Bind inputs by element count (robust to metadata ordering):
    //   x: 128*14 = 1792, q_weights: 3*14*3 = 126, w_lin: 14, b_lin: 1
    const float* x    = nullptr;
    const float* qw   = nullptr;
    const float* wlin = nullptr;
    const float* blin = nullptr;
    for (int i = 0; i < n_in; i++) {
        switch (in_sizes[i]) {
            case 1792: x    = (const float*)d_in[i]; break;
            case 126:  qw   = (const float*)d_in[i]; break;
            case 14:   wlin = (const float*)d_in[i]; break;
            case 1:    blin = (const float*)d_in[i]; break;
            default: break;
        }
    }
    float* out = (float*)d_out;                  // (128, 1)

    cudaFuncSetAttribute(qsim_kernel,
                         cudaFuncAttributeMaxDynamicSharedMemorySize,
                         SMEM_BYTES);

    qsim_kernel<<<128, TPB, SMEM_BYTES>>>(x, qw, wlin, blin, out);
}

// round 9
// speedup vs baseline: 1.2999x; 1.2999x over previous
#include <cuda_runtime.h>

#define NQ   14
#define DIM  (1 << NQ)       // 16384
#define NL   3
#define TPB  512
#define SMEM_BYTES (DIM * sizeof(float2))   // 131072

struct C2x2 { float r00, i00, r01, i01, r10, i10, r11, i11; };

__device__ __forceinline__ C2x2 rot_gate(float phi, float th, float om)
{
    float ct, st, ca, sa, cb, sb;
    sincosf(0.5f * th,         &st, &ct);
    sincosf(0.5f * (phi + om), &sa, &ca);
    sincosf(0.5f * (phi - om), &sb, &cb);
    // Rot = [[e^{-i(phi+om)/2} ct, -e^{+i(phi-om)/2} st],
    //        [e^{-i(phi-om)/2} st,  e^{+i(phi+om)/2} ct]]
    C2x2 g;
    g.r00 =  ct * ca; g.i00 = -ct * sa;
    g.r01 = -st * cb; g.i01 = -st * sb;
    g.r10 =  st * cb; g.i10 = -st * sb;
    g.r11 =  ct * ca; g.i11 =  ct * sa;
    return g;
}

__device__ __forceinline__ void apply2(const C2x2& g, float2& a0, float2& a1)
{
    float2 n0, n1;
    n0.x = g.r00 * a0.x - g.i00 * a0.y + g.r01 * a1.x - g.i01 * a1.y;
    n0.y = g.r00 * a0.y + g.i00 * a0.x + g.r01 * a1.y + g.i01 * a1.x;
    n1.x = g.r10 * a0.x - g.i10 * a0.y + g.r11 * a1.x - g.i11 * a1.y;
    n1.y = g.r10 * a0.y + g.i10 * a0.x + g.r11 * a1.y + g.i11 * a1.x;
    a0 = n0; a1 = n1;
}

__global__ __launch_bounds__(TPB, 1)
void qsim_kernel(const float* __restrict__ x,
                 const float* __restrict__ qw,
                 const float* __restrict__ wlin,
                 const float* __restrict__ blin,
                 float* __restrict__ out)
{
    extern __shared__ float2 s[];         // statevector, 128 KB
    __shared__ float red[TPB / 32];

    const int b   = blockIdx.x;
    const int tid = threadIdx.x;

    // ---- init: product state from RX embedding applied to |0...0> ----
    // RX(x)|0> = cos(x/2)|0> - i sin(x/2)|1>  ->  amp(i) = prod * (-i)^popc(i)
    float cw[NQ], sw[NQ];
    #pragma unroll
    for (int w = 0; w < NQ; w++)
        sincosf(0.5f * x[b * NQ + w], &sw[w], &cw[w]);

    for (int i = tid; i < DIM; i += TPB) {
        float mag = 1.0f;
        #pragma unroll
        for (int w = 0; w < NQ; w++)
            mag *= (((i >> (NQ - 1 - w)) & 1) ? sw[w] : cw[w]);
        int k = __popc(i) & 3;
        float2 v;
        v.x = (k == 0) ? mag : ((k == 2) ? -mag : 0.0f);
        v.y = (k == 3) ? mag : ((k == 1) ? -mag : 0.0f);
        s[i] = v;
    }

    // ---- StronglyEntanglingLayers ----
    for (int l = 0; l < NL; l++) {
        // Rot gates fused in adjacent-wire pairs: wires (2t, 2t+1) -> bits (b1, b2=b1-1)
        for (int t = 0; t < NQ / 2; t++) {
            int w1 = 2 * t, w2 = 2 * t + 1;
            C2x2 g1 = rot_gate(qw[(l * NQ + w1) * 3 + 0],
                               qw[(l * NQ + w1) * 3 + 1],
                               qw[(l * NQ + w1) * 3 + 2]);
            C2x2 g2 = rot_gate(qw[(l * NQ + w2) * 3 + 0],
                               qw[(l * NQ + w2) * 3 + 1],
                               qw[(l * NQ + w2) * 3 + 2]);
            int b1 = NQ - 1 - w1;          // higher bit
            int b2 = b1 - 1;               // lower bit (wire w2)
            unsigned lowm = (1u << b2) - 1u;

            __syncthreads();
            #pragma unroll 2
            for (int p = tid; p < DIM / 4; p += TPB) {
                unsigned base = (((unsigned)p >> b2) << (b2 + 2)) | ((unsigned)p & lowm);
                unsigned i01 = base | (1u << b2);
                unsigned i10 = base | (1u << b1);
                unsigned i11 = i10  | (1u << b2);
                float2 v00 = s[base];
                float2 v01 = s[i01];
                float2 v10 = s[i10];
                float2 v11 = s[i11];
                // gate on wire w1 (bit b1): pairs (v00,v10), (v01,v11)
                apply2(g1, v00, v10);
                apply2(g1, v01, v11);
                // gate on wire w2 (bit b2): pairs (v00,v01), (v10,v11)
                apply2(g2, v00, v01);
                apply2(g2, v10, v11);
                s[base] = v00;
                s[i01]  = v01;
                s[i10]  = v10;
                s[i11]  = v11;
            }
        }
        // CNOT ring: control w, target (w+r)%n, r = l+1.
        // Last layer's ring is folded into the expval signs below (pure permutation
        // of probabilities), so only layers 0..NL-2 move data.
        if (l < NL - 1) {
            int r = l + 1;
            for (int w = 0; w < NQ; w++) {
                int bc = NQ - 1 - w;               // control bit
                int bt = NQ - 1 - ((w + r) % NQ);  // target bit
                int hi = bc > bt ? bc : bt;
                int lo = bc > bt ? bt : bc;
                unsigned lowmask = (1u << lo) - 1u;
                unsigned himask  = (1u << hi) - 1u;
                __syncthreads();
                for (int p = tid; p < DIM / 4; p += TPB) {
                    unsigned t1 = (((unsigned)p >> lo) << (lo + 1)) | ((unsigned)p & lowmask);
                    unsigned i0 = ((t1 >> hi) << (hi + 1)) | (t1 & himask);
                    i0 |= (1u << bc);              // control = 1, target = 0
                    unsigned i1 = i0 | (1u << bt); // control = 1, target = 1
                    float2 a0 = s[i0];
                    float2 a1 = s[i1];
                    s[i0] = a1;                    // swap amplitudes
                    s[i1] = a0;
                }
            }
        }
    }
    __syncthreads();

    // ---- last CNOT ring folded into expval signs ----
    // psi_final[j] = psi_pre[N j] with N^{-1} = C_14 ... C_1 built by row-xors in
    // circuit order. <Z_w> = sum_i |psi_pre[i]|^2 * (-1)^{row_{13-w}(N^{-1}) . i}
    unsigned Ar[NQ];
    #pragma unroll
    for (int i = 0; i < NQ; i++) Ar[i] = 1u << i;
    {
        int r = NL;  // last layer ring range = (NL-1)+1
        #pragma unroll
        for (int w = 0; w < NQ; w++) {
            int bc = NQ - 1 - w;
            int bt = NQ - 1 - ((w + r) % NQ);
            Ar[bt] ^= Ar[bc];
        }
    }
    float    wl[NQ];
    unsigned rf[NQ];
    #pragma unroll
    for (int w = 0; w < NQ; w++) { wl[w] = wlin[w]; rf[w] = Ar[NQ - 1 - w]; }

    float acc = 0.0f;
    for (int i = tid; i < DIM; i += TPB) {
        float2 a = s[i];
        float  pr = a.x * a.x + a.y * a.y;
        float  z = 0.0f;
        #pragma unroll
        for (int w = 0; w < NQ; w++)
            z += ((__popc(rf[w] & (unsigned)i) & 1) ? -wl[w] : wl[w]);
        acc += pr * z;
    }
    #pragma unroll
    for (int off = 16; off; off >>= 1)
        acc += __shfl_down_sync(0xffffffffu, acc, off);
    if ((tid & 31) == 0) red[tid >> 5] = acc;
    __syncthreads();
    if (tid == 0) {
        float t = 0.0f;
        #pragma unroll
        for (int q = 0; q < TPB / 32; q++) t += red[q];
        out[b] = t + blin[0];
    }
}

extern "C" void kernel_launch(void* const* d_in, const int* in_sizes, int n_in,
                              void* d_out, int out_size)
{
    // Bind inputs by element count (robust to metadata ordering):
    //   x: 128*14 = 1792, q_weights: 3*14*3 = 126, w_lin: 14, b_lin: 1
    const float* x    = nullptr;
    const float* qw   = nullptr;
    const float* wlin = nullptr;
    const float* blin = nullptr;
    for (int i = 0; i < n_in; i++) {
        switch (in_sizes[i]) {
            case 1792: x    = (const float*)d_in[i]; break;
            case 126:  qw   = (const float*)d_in[i]; break;
            case 14:   wlin = (const float*)d_in[i]; break;
            case 1:    blin = (const float*)d_in[i]; break;
            default: break;
        }
    }
    float* out = (float*)d_out;                  // (128, 1)

    cudaFuncSetAttribute(qsim_kernel,
                         cudaFuncAttributeMaxDynamicSharedMemorySize,
                         SMEM_BYTES);

    qsim_kernel<<<128, TPB, SMEM_BYTES>>>(x, qw, wlin, blin, out);
}

// round 11
// speedup vs baseline: 2.7413x; 2.1089x over previous
#include <cuda_runtime.h>

#define NQ   14
#define DIM  (1 << NQ)       // 16384
#define NL   3
#define TPB  512
#define AMPS 32              // DIM / TPB
#define SMEM_BYTES (DIM * sizeof(float2))   // 131072

struct C2x2 { float r00, i00, r01, i01, r10, i10, r11, i11; };

__device__ __forceinline__ C2x2 rot_gate(float phi, float th, float om)
{
    float ct, st, ca, sa, cb, sb;
    sincosf(0.5f * th,         &st, &ct);
    sincosf(0.5f * (phi + om), &sa, &ca);
    sincosf(0.5f * (phi - om), &sb, &cb);
    C2x2 g;
    g.r00 =  ct * ca; g.i00 = -ct * sa;
    g.r01 = -st * cb; g.i01 = -st * sb;
    g.r10 =  st * cb; g.i10 = -st * sb;
    g.r11 =  ct * ca; g.i11 =  ct * sa;
    return g;
}

__device__ __forceinline__ void apply2(const C2x2& g, float2& a0, float2& a1)
{
    float2 n0, n1;
    n0.x = g.r00 * a0.x - g.i00 * a0.y + g.r01 * a1.x - g.i01 * a1.y;
    n0.y = g.r00 * a0.y + g.i00 * a0.x + g.r01 * a1.y + g.i01 * a1.x;
    n1.x = g.r10 * a0.x - g.i10 * a0.y + g.r11 * a1.x - g.i11 * a1.y;
    n1.y = g.r10 * a0.y + g.i10 * a0.x + g.r11 * a1.y + g.i11 * a1.x;
    a0 = n0; a1 = n1;
}

// bank-conflict-avoiding SMEM swizzle (pure relabeling; used on EVERY s[] access)
__device__ __forceinline__ unsigned swz(unsigned a) { return a ^ ((a >> 5) & 31u); }

__global__ __launch_bounds__(TPB, 1)
void qsim_kernel(const float* __restrict__ x,
                 const float* __restrict__ qw,
                 const float* __restrict__ wlin,
                 const float* __restrict__ blin,
                 float* __restrict__ out)
{
    extern __shared__ float2 s[];             // 128 KB exchange buffer
    __shared__ C2x2 sg[NL * NQ];              // precomputed Rot gates
    __shared__ float red[TPB / 32];

    const int t    = threadIdx.x;
    const int lane = t & 31;
    const int b    = blockIdx.x;

    float2 r[AMPS];                           // this thread's 32 amplitudes

    // ---- cooperative gate precompute: one thread per (layer,wire) ----
    if (t < NL * NQ)
        sg[t] = rot_gate(qw[t * 3 + 0], qw[t * 3 + 1], qw[t * 3 + 2]);

    // ---- init in registers: RX product state on |0..0> ----
    // Phase-A mapping: logical index y = (t<<5) | u  (u = register index, bits 0-4)
    // y bit (5+j) = t bit j  -> wire 8-j ;  y bit q (q<5) -> wire 13-q
    float tmag = 1.0f;
    #pragma unroll
    for (int j = 0; j < 9; j++) {
        float sv, cv;
        sincosf(0.5f * x[b * NQ + (8 - j)], &sv, &cv);
        tmag *= ((t >> j) & 1) ? sv : cv;
    }
    float su[5], cu[5];
    #pragma unroll
    for (int q = 0; q < 5; q++)
        sincosf(0.5f * x[b * NQ + (13 - q)], &su[q], &cu[q]);
    const int tp = __popc((unsigned)t);
    #pragma unroll
    for (int u = 0; u < AMPS; u++) {
        float m = tmag;
        #pragma unroll
        for (int q = 0; q < 5; q++)
            m *= ((u >> q) & 1) ? su[q] : cu[q];
        int k = (tp + __popc((unsigned)u)) & 3;      // (-i)^popc(y)
        r[u] = make_float2((k == 0) ? m : ((k == 2) ? -m : 0.0f),
                           (k == 3) ? m : ((k == 1) ? -m : 0.0f));
    }
    __syncthreads();                                 // sg[] ready

    for (int l = 0; l < NL; l++) {
        // ---- Phase A load (layers 1,2): gather with previous ring folded in ----
        // psi_new[y] = psi_old[F(y)],  F = ring map built by ops w=13..0 (descending);
        // its inverse (ascending build) is the numerically-validated sign-fold matrix.
        if (l > 0) {
            const int rr = l;                        // previous layer's ring range
            unsigned Fcol[NQ];
            #pragma unroll
            for (int j = 0; j < NQ; j++) {
                unsigned z = 1u << j;
                for (int w = NQ - 1; w >= 0; w--) {
                    int bc = NQ - 1 - w;
                    int bt = NQ - 1 - ((w + rr) % NQ);
                    z ^= ((z >> bc) & 1u) << bt;
                }
                Fcol[j] = z;
            }
            unsigned Fb = 0;
            #pragma unroll
            for (int j = 0; j < 9; j++)
                if ((t >> j) & 1) Fb ^= Fcol[5 + j];
            #pragma unroll
            for (int u = 0; u < AMPS; u++) {
                unsigned fy = Fb;
                if (u & 1)  fy ^= Fcol[0];
                if (u & 2)  fy ^= Fcol[1];
                if (u & 4)  fy ^= Fcol[2];
                if (u & 8)  fy ^= Fcol[3];
                if (u & 16) fy ^= Fcol[4];
                r[u] = s[swz(fy)];
            }
        }

        // ---- Phase A gates: wires 9-13 (register bits 0-4), wires 5-8 (lane bits 0-3) ----
        #pragma unroll
        for (int q = 0; q < 5; q++) {                // wire 13-q on register bit q
            C2x2 g = sg[l * NQ + (13 - q)];
            #pragma unroll
            for (int k = 0; k < AMPS; k++)
                if (!(k & (1 << q))) apply2(g, r[k], r[k | (1 << q)]);
        }
        #pragma unroll
        for (int ql = 0; ql < 4; ql++) {             // wire 8-ql on lane bit ql
            C2x2 g = sg[l * NQ + (8 - ql)];
            int bit = (lane >> ql) & 1;
            float gar = bit ? g.r11 : g.r00, gai = bit ? g.i11 : g.i00;
            float gbr = bit ? g.r10 : g.r01, gbi = bit ? g.i10 : g.i01;
            #pragma unroll
            for (int k = 0; k < AMPS; k++) {
                float ox = __shfl_xor_sync(0xffffffffu, r[k].x, 1 << ql);
                float oy = __shfl_xor_sync(0xffffffffu, r[k].y, 1 << ql);
                float nx = gar * r[k].x - gai * r[k].y + gbr * ox - gbi * oy;
                float ny = gar * r[k].y + gai * r[k].x + gbr * oy + gbi * ox;
                r[k] = make_float2(nx, ny);
            }
        }

        __syncthreads();                             // all phase-A loads done
        #pragma unroll
        for (int u = 0; u < AMPS; u++)               // store contiguous layout
            s[swz((unsigned)(t << 5) | u)] = r[u];
        __syncthreads();                             // stores visible

        // ---- Phase B: logical y = (u<<9) | t  (bits 9-13 register-local) ----
        #pragma unroll
        for (int u = 0; u < AMPS; u++)
            r[u] = s[swz(((unsigned)u << 9) | (unsigned)t)];

        #pragma unroll
        for (int q = 0; q < 5; q++) {                // wire 4-q on register bit q (y bit 9+q)
            C2x2 g = sg[l * NQ + (4 - q)];
            #pragma unroll
            for (int k = 0; k < AMPS; k++)
                if (!(k & (1 << q))) apply2(g, r[k], r[k | (1 << q)]);
        }

        if (l < NL - 1) {
            __syncthreads();                         // all phase-B loads done
            #pragma unroll
            for (int u = 0; u < AMPS; u++)
                s[swz(((unsigned)u << 9) | (unsigned)t)] = r[u];
            __syncthreads();                         // stores visible for next A-load
        }
    }

    // ---- last CNOT ring (r = NL) folded into expval signs (validated recurrence) ----
    unsigned Ar[NQ];
    #pragma unroll
    for (int i = 0; i < NQ; i++) Ar[i] = 1u << i;
    {
        const int rr = NL;
        #pragma unroll
        for (int w = 0; w < NQ; w++) {
            int bc = NQ - 1 - w;
            int bt = NQ - 1 - ((w + rr) % NQ);
            Ar[bt] ^= Ar[bc];
        }
    }
    float    wl[NQ];
    unsigned rf[NQ];
    #pragma unroll
    for (int w = 0; w < NQ; w++) { wl[w] = wlin[w]; rf[w] = Ar[NQ - 1 - w]; }

    float acc = 0.0f;
    #pragma unroll
    for (int u = 0; u < AMPS; u++) {
        unsigned y = ((unsigned)u << 9) | (unsigned)t;
        float pr = r[u].x * r[u].x + r[u].y * r[u].y;
        float z  = 0.0f;
        #pragma unroll
        for (int w = 0; w < NQ; w++)
            z += ((__popc(rf[w] & y) & 1) ? -wl[w] : wl[w]);
        acc += pr * z;
    }
    #pragma unroll
    for (int off = 16; off; off >>= 1)
        acc += __shfl_down_sync(0xffffffffu, acc, off);
    if ((lane) == 0) red[t >> 5] = acc;
    __syncthreads();
    if (t == 0) {
        float tot = 0.0f;
        #pragma unroll
        for (int q = 0; q < TPB / 32; q++) tot += red[q];
        out[b] = tot + blin[0];
    }
}

extern "C" void kernel_launch(void* const* d_in, const int* in_sizes, int n_in,
                              void* d_out, int out_size)
{
    // Bind inputs by element count (robust to metadata ordering):
    //   x: 128*14 = 1792, q_weights: 3*14*3 = 126, w_lin: 14, b_lin: 1
    const float* x    = nullptr;
    const float* qw   = nullptr;
    const float* wlin = nullptr;
    const float* blin = nullptr;
    for (int i = 0; i < n_in; i++) {
        switch (in_sizes[i]) {
            case 1792: x    = (const float*)d_in[i]; break;
            case 126:  qw   = (const float*)d_in[i]; break;
            case 14:   wlin = (const float*)d_in[i]; break;
            case 1:    blin = (const float*)d_in[i]; break;
            default: break;
        }
    }
    float* out = (float*)d_out;                  // (128, 1)

    cudaFuncSetAttribute(qsim_kernel,
                         cudaFuncAttributeMaxDynamicSharedMemorySize,
                         SMEM_BYTES);

    qsim_kernel<<<128, TPB, SMEM_BYTES>>>(x, qw, wlin, blin, out);
}